// round 3
// baseline (speedup 1.0000x reference)
#include <cuda_runtime.h>
#include <math_constants.h>

#define NTOK  2048
#define FFN   2048

// ---------------- scratch ----------------
__device__ float g_q   [NTOK * 1024];
__device__ float g_kt  [2 * 1024 * 1024];
__device__ float g_v   [NTOK * 1024];
__device__ float g_gate[NTOK * 1024];
__device__ float g_s   [(size_t)2 * 16 * 1024 * 1024];
__device__ float g_o   [NTOK * 1024];
__device__ float g_r1  [NTOK * 1024];
__device__ float g_y   [NTOK * 1024];
__device__ float g_u   [NTOK * FFN];
__device__ float g_r2  [NTOK * 1024];

enum { EPI_PROJ4 = 0, EPI_SCOREBIAS = 1, EPI_GATE = 2, EPI_RESBIAS = 3, EPI_SILU = 4 };

struct XArgs {
    const float* Bw1; const float* Bw2; const float* Bw3;  // wk, wv, wg
    float* Ckt; float* Cv; float* Cg;                      // kt, v, gate outputs
    const float* bg;                                       // gate bias
    const float* eb;                                       // edge bias [b,q,k,h]
};

__device__ __forceinline__ unsigned f2tf32(float f) {
    unsigned r;
    asm("cvt.rna.tf32.f32 %0, %1;" : "=r"(r) : "f"(f));
    return r;
}

__device__ __forceinline__ void mma_tf32(float* c, const unsigned* a, const unsigned* b) {
    asm volatile(
        "mma.sync.aligned.m16n8k8.row.col.f32.tf32.tf32.f32 "
        "{%0,%1,%2,%3}, {%4,%5,%6,%7}, {%8,%9}, {%0,%1,%2,%3};"
        : "+f"(c[0]), "+f"(c[1]), "+f"(c[2]), "+f"(c[3])
        : "r"(a[0]), "r"(a[1]), "r"(a[2]), "r"(a[3]), "r"(b[0]), "r"(b[1]));
}

// ============ TF32 GEMM v2: pre-converted tf32 smem, reg-staged =============
template<int BN, int EPI, bool ZX>
__global__ __launch_bounds__(256, (BN == 128) ? 2 : 1)
void tgemm2(const float* __restrict__ A, const float* __restrict__ B,
            float* __restrict__ C, int M, int N, int K,
            int lda, int ldb, int ldc, int zdiv,
            long long sA1, long long sA2, long long sB1, long long sB2,
            long long sC1, long long sC2,
            const float* __restrict__ bias, const float* __restrict__ res,
            const unsigned char* __restrict__ mask, float scale, XArgs xa)
{
    constexpr int BM = 128, BK = 16, AS = 20, BS = BN + 8;
    constexpr int WTM = (BN == 128) ? 32 : 64;
    constexpr int WRM = 128 / WTM;
    constexpr int MT = WTM / 16;
    constexpr int NT = 8;

    extern __shared__ unsigned smemu[];
    unsigned* Asm = smemu;                 // [2][128][AS]
    unsigned* Bsm = smemu + 2 * BM * AS;   // [2][16][BS]

    int z, bn, bm;
    if (ZX) { z = blockIdx.x; bn = blockIdx.y; bm = blockIdx.z; }
    else    { z = blockIdx.z; bn = blockIdx.x; bm = blockIdx.y; }
    int z1 = z / zdiv, z2 = z - z1 * zdiv;
    A += (size_t)z1 * sA1 + (size_t)z2 * sA2;
    size_t coff = (size_t)z1 * sC1 + (size_t)z2 * sC2;

    const float* Bbase = B;
    int bnoff = bn * BN;
    int bsel = 0;
    if (EPI == EPI_PROJ4) {
        bsel = bn >> 2;
        bnoff = (bn & 3) * 256;
        Bbase = (bsel == 0) ? B : (bsel == 1) ? xa.Bw1 : (bsel == 2) ? xa.Bw2 : xa.Bw3;
    } else {
        Bbase += (size_t)z1 * sB1 + (size_t)z2 * sB2;
    }

    int tid = threadIdx.x, lane = tid & 31, wid = tid >> 5;
    int wm = (wid % WRM) * WTM;
    int wn = (wid / WRM) * 64;

    const float* Ag = A + (size_t)(bm * BM) * lda;
    const float* Bg = Bbase + bnoff;

    float acc[MT][NT][4] = {};

    constexpr int ALD = (BM * BK) / (256 * 4);   // 2
    constexpr int BLD = (BK * BN) / (256 * 4);   // 2 or 4
    float4 arg_[ALD], brg_[BLD];
    int arow[ALD], acol[ALD], browi[BLD], bcoli[BLD];
    bool bvalid[BLD];
#pragma unroll
    for (int i = 0; i < ALD; i++) { int f = tid + 256 * i; arow[i] = f >> 2; acol[i] = (f & 3) * 4; }
#pragma unroll
    for (int i = 0; i < BLD; i++) {
        int f = tid + 256 * i;
        browi[i] = f / (BN / 4);
        bcoli[i] = (f % (BN / 4)) * 4;
        bvalid[i] = (bnoff + bcoli[i]) < N;
    }

    int KT = K / BK;

    // prologue
#pragma unroll
    for (int i = 0; i < ALD; i++)
        arg_[i] = *(const float4*)(Ag + (size_t)arow[i] * lda + acol[i]);
#pragma unroll
    for (int i = 0; i < BLD; i++)
        brg_[i] = bvalid[i] ? *(const float4*)(Bg + (size_t)browi[i] * ldb + bcoli[i])
                            : make_float4(0.f, 0.f, 0.f, 0.f);
    {
        unsigned* Ad = Asm; unsigned* Bd = Bsm;
#pragma unroll
        for (int i = 0; i < ALD; i++) {
            uint4 u = { f2tf32(arg_[i].x), f2tf32(arg_[i].y), f2tf32(arg_[i].z), f2tf32(arg_[i].w) };
            *(uint4*)(Ad + arow[i] * AS + acol[i]) = u;
        }
#pragma unroll
        for (int i = 0; i < BLD; i++) {
            uint4 u = { f2tf32(brg_[i].x), f2tf32(brg_[i].y), f2tf32(brg_[i].z), f2tf32(brg_[i].w) };
            *(uint4*)(Bd + browi[i] * BS + bcoli[i]) = u;
        }
    }
    __syncthreads();

    for (int kt = 0; kt < KT; kt++) {
        int st = kt & 1;
        if (kt + 1 < KT) {
            int k0 = (kt + 1) * BK;
#pragma unroll
            for (int i = 0; i < ALD; i++)
                arg_[i] = *(const float4*)(Ag + (size_t)arow[i] * lda + k0 + acol[i]);
#pragma unroll
            for (int i = 0; i < BLD; i++)
                brg_[i] = bvalid[i] ? *(const float4*)(Bg + (size_t)(k0 + browi[i]) * ldb + bcoli[i])
                                    : make_float4(0.f, 0.f, 0.f, 0.f);
        }

        const unsigned* Ar = Asm + st * BM * AS;
        const unsigned* Br = Bsm + st * BK * BS;
#pragma unroll
        for (int kk = 0; kk < 16; kk += 8) {
            unsigned a[MT][4], b[NT][2];
            int ar = lane >> 2, ac = kk + (lane & 3);
#pragma unroll
            for (int m_ = 0; m_ < MT; m_++) {
                int r = wm + m_ * 16 + ar;
                a[m_][0] = Ar[r * AS + ac];
                a[m_][1] = Ar[(r + 8) * AS + ac];
                a[m_][2] = Ar[r * AS + ac + 4];
                a[m_][3] = Ar[(r + 8) * AS + ac + 4];
            }
            int br = kk + (lane & 3), bc = wn + (lane >> 2);
#pragma unroll
            for (int n_ = 0; n_ < NT; n_++) {
                b[n_][0] = Br[br * BS + bc + n_ * 8];
                b[n_][1] = Br[(br + 4) * BS + bc + n_ * 8];
            }
#pragma unroll
            for (int m_ = 0; m_ < MT; m_++)
#pragma unroll
                for (int n_ = 0; n_ < NT; n_++)
                    mma_tf32(acc[m_][n_], a[m_], b[n_]);
        }

        if (kt + 1 < KT) {
            int ns = st ^ 1;
            unsigned* Ad = Asm + ns * BM * AS;
            unsigned* Bd = Bsm + ns * BK * BS;
#pragma unroll
            for (int i = 0; i < ALD; i++) {
                uint4 u = { f2tf32(arg_[i].x), f2tf32(arg_[i].y), f2tf32(arg_[i].z), f2tf32(arg_[i].w) };
                *(uint4*)(Ad + arow[i] * AS + acol[i]) = u;
            }
#pragma unroll
            for (int i = 0; i < BLD; i++) {
                uint4 u = { f2tf32(brg_[i].x), f2tf32(brg_[i].y), f2tf32(brg_[i].z), f2tf32(brg_[i].w) };
                *(uint4*)(Bd + browi[i] * BS + bcoli[i]) = u;
            }
        }
        __syncthreads();
    }

    // epilogue
#pragma unroll
    for (int m_ = 0; m_ < MT; m_++) {
#pragma unroll
        for (int n_ = 0; n_ < NT; n_++) {
#pragma unroll
            for (int e = 0; e < 4; e++) {
                int m = bm * BM + wm + m_ * 16 + (lane >> 2) + (e >> 1) * 8;
                int n = bnoff + wn + n_ * 8 + (lane & 3) * 2 + (e & 1);
                if (n >= N) continue;
                float v = acc[m_][n_][e];
                size_t idx = coff + (size_t)m * ldc + n;
                if (EPI == EPI_PROJ4) {
                    if (bsel == 0) {
                        C[idx] = v * 0.125f;
                    } else if (bsel == 1) {
                        size_t o = (size_t)(m >> 10) * (1u << 20) + (size_t)n * 1024 + (m & 1023);
                        xa.Ckt[o] = v;
                    } else if (bsel == 2) {
                        xa.Cv[idx] = v;
                    } else {
                        float zz = v + xa.bg[n];
                        xa.Cg[idx] = 1.f / (1.f + __expf(-zz));
                    }
                } else if (EPI == EPI_SCOREBIAS) {
                    float t = v + xa.eb[((size_t)(z1 * 1024 + m) * 1024 + n) * 16 + z2];
                    if (mask[z1 * 1024 + n]) t = -CUDART_INF_F;
                    C[idx] = t;
                } else if (EPI == EPI_GATE) {
                    C[idx] = v * res[idx];
                } else if (EPI == EPI_RESBIAS) {
                    C[idx] = v + bias[n] + res[idx];
                } else if (EPI == EPI_SILU) {
                    float zz = v + bias[n];
                    C[idx] = zz / (1.f + __expf(-zz));
                }
            }
        }
    }
}

// ------- softmax over k; probs back to g_s and d_out [b,q,k,h] -------------
__global__ __launch_bounds__(512)
void softmax_kernel(float* __restrict__ s, float* __restrict__ attn_out)
{
    int q = blockIdx.x;
    int b = blockIdx.y;
    int w    = threadIdx.x >> 5;
    int lane = threadIdx.x & 31;
    float* row = s + (((size_t)(b * 16 + w) * 1024 + q)) * 1024;

    float v[32];
    float mx = -CUDART_INF_F;
#pragma unroll
    for (int i = 0; i < 32; i++) {
        v[i] = row[i * 32 + lane];
        mx = fmaxf(mx, v[i]);
    }
#pragma unroll
    for (int o = 16; o; o >>= 1) mx = fmaxf(mx, __shfl_xor_sync(0xffffffffu, mx, o));
    float sum = 0.f;
#pragma unroll
    for (int i = 0; i < 32; i++) { v[i] = __expf(v[i] - mx); sum += v[i]; }
#pragma unroll
    for (int o = 16; o; o >>= 1) sum += __shfl_xor_sync(0xffffffffu, sum, o);
    float inv = 1.f / sum;
#pragma unroll
    for (int i = 0; i < 32; i++) { v[i] *= inv; row[i * 32 + lane] = v[i]; }

    __shared__ float tile[16 * 513];
    float* out = attn_out + ((size_t)(b * 1024 + q)) * 16384;
#pragma unroll
    for (int half = 0; half < 2; half++) {
        __syncthreads();
#pragma unroll
        for (int i = 0; i < 16; i++) {
            int k = (half * 16 + i) * 32 + lane;
            tile[w * 513 + (k - half * 512)] = v[half * 16 + i];
        }
        __syncthreads();
        for (int idx = threadIdx.x; idx < 8192; idx += 512) {
            int k = idx >> 4, h = idx & 15;
            out[half * 8192 + idx] = tile[h * 513 + k];
        }
    }
}

// ---------------- row LayerNorm over D=1024 --------------------------------
__global__ __launch_bounds__(256)
void ln_kernel(const float* __restrict__ in, float* __restrict__ out,
               const float* __restrict__ gg, const float* __restrict__ bb)
{
    int row = blockIdx.x;
    int tid = threadIdx.x;
    float4 v = reinterpret_cast<const float4*>(in + (size_t)row * 1024)[tid];
    float s  = v.x + v.y + v.z + v.w;
    float ss = v.x * v.x + v.y * v.y + v.z * v.z + v.w * v.w;
#pragma unroll
    for (int o = 16; o; o >>= 1) {
        s  += __shfl_xor_sync(0xffffffffu, s, o);
        ss += __shfl_xor_sync(0xffffffffu, ss, o);
    }
    __shared__ float rs[8], rss[8];
    if ((tid & 31) == 0) { rs[tid >> 5] = s; rss[tid >> 5] = ss; }
    __syncthreads();
    if (tid < 32) {
        float a = (tid < 8) ? rs[tid] : 0.f;
        float c = (tid < 8) ? rss[tid] : 0.f;
#pragma unroll
        for (int o = 4; o; o >>= 1) {
            a += __shfl_xor_sync(0xffffffffu, a, o);
            c += __shfl_xor_sync(0xffffffffu, c, o);
        }
        if (tid == 0) { rs[0] = a; rss[0] = c; }
    }
    __syncthreads();
    float mean = rs[0] * (1.f / 1024.f);
    float var  = rss[0] * (1.f / 1024.f) - mean * mean;
    float inv  = rsqrtf(var + 1e-5f);
    float4 g4 = ((const float4*)gg)[tid];
    float4 b4 = ((const float4*)bb)[tid];
    float4 o4;
    o4.x = (v.x - mean) * inv * g4.x + b4.x;
    o4.y = (v.y - mean) * inv * g4.y + b4.y;
    o4.z = (v.z - mean) * inv * g4.z + b4.z;
    o4.w = (v.w - mean) * inv * g4.w + b4.w;
    reinterpret_cast<float4*>(out + (size_t)row * 1024)[tid] = o4;
}

// ---------------- launcher --------------------------------------------------
extern "C" void kernel_launch(void* const* d_in, const int* in_sizes, int n_in,
                              void* d_out, int out_size)
{
    const float* x    = (const float*)d_in[0];
    const float* eb   = (const float*)d_in[1];
    const unsigned char* mask = (const unsigned char*)d_in[2];
    const float* wq   = (const float*)d_in[3];
    const float* wk   = (const float*)d_in[4];
    const float* wv   = (const float*)d_in[5];
    const float* wo   = (const float*)d_in[6];
    const float* bo   = (const float*)d_in[7];
    const float* wg   = (const float*)d_in[8];
    const float* bg   = (const float*)d_in[9];
    const float* w1   = (const float*)d_in[10];
    const float* b1   = (const float*)d_in[11];
    const float* w2   = (const float*)d_in[12];
    const float* b2   = (const float*)d_in[13];
    const float* ln1g = (const float*)d_in[14];
    const float* ln1b = (const float*)d_in[15];
    const float* ln2g = (const float*)d_in[16];
    const float* ln2b = (const float*)d_in[17];

    float* out_x    = (float*)d_out;
    float* out_attn = (float*)d_out + (size_t)NTOK * 1024;

    float *q, *kt, *v, *g, *s, *o, *r1, *y, *u, *r2;
    cudaGetSymbolAddress((void**)&q,  g_q);
    cudaGetSymbolAddress((void**)&kt, g_kt);
    cudaGetSymbolAddress((void**)&v,  g_v);
    cudaGetSymbolAddress((void**)&g,  g_gate);
    cudaGetSymbolAddress((void**)&s,  g_s);
    cudaGetSymbolAddress((void**)&o,  g_o);
    cudaGetSymbolAddress((void**)&r1, g_r1);
    cudaGetSymbolAddress((void**)&y,  g_y);
    cudaGetSymbolAddress((void**)&u,  g_u);
    cudaGetSymbolAddress((void**)&r2, g_r2);

    const int SM128 = (2 * 128 * 20 + 2 * 16 * 136) * 4;   // 37888
    const int SM256 = (2 * 128 * 20 + 2 * 16 * 264) * 4;   // 54272
    cudaFuncSetAttribute(tgemm2<256, EPI_PROJ4, false>,
                         cudaFuncAttributeMaxDynamicSharedMemorySize, SM256);
    cudaFuncSetAttribute(tgemm2<256, EPI_SCOREBIAS, true>,
                         cudaFuncAttributeMaxDynamicSharedMemorySize, SM256);

    XArgs xa{};
    xa.bg = bg; xa.eb = eb;

    // 1) fused projections: q(scaled), kt(transposed), v, gate   [one launch]
    {
        XArgs pa = xa;
        pa.Bw1 = wk; pa.Bw2 = wv; pa.Bw3 = wg;
        pa.Ckt = kt; pa.Cv = v;  pa.Cg = g;
        tgemm2<256, EPI_PROJ4, false><<<dim3(16, 16, 1), 256, SM256>>>(
            x, wq, q, NTOK, 1024, 1024, 1024, 1024, 1024,
            1, 0, 0, 0, 0, 0, 0, nullptr, nullptr, nullptr, 1.f, pa);
    }

    // 2) scores = Q_h @ Kt_h + edge_bias (read direct, z-fastest for L2 reuse)
    tgemm2<256, EPI_SCOREBIAS, true><<<dim3(32, 4, 8), 256, SM256>>>(
        q, kt, s, 1024, 1024, 64, 1024, 1024, 1024,
        16,
        (long long)1048576, 64,
        (long long)1048576, 65536,
        (long long)16777216, 1048576,
        nullptr, nullptr, mask, 1.f, xa);

    // 3) softmax over keys; probs to g_s and d_out [b,q,k,h]
    softmax_kernel<<<dim3(1024, 2), 512>>>(s, out_attn);

    // 4) o = (probs @ V_h) * gate
    tgemm2<128, EPI_GATE, true><<<dim3(32, 1, 8), 256, SM128>>>(
        s, v, o, 1024, 64, 1024, 1024, 1024, 1024,
        16,
        (long long)16777216, 1048576,
        (long long)1048576, 64,
        (long long)1048576, 64,
        nullptr, g, nullptr, 1.f, xa);

    // 5) r1 = o @ wo + bo + x ; LN1 -> y
    tgemm2<128, EPI_RESBIAS, false><<<dim3(8, 16, 1), 256, SM128>>>(
        o, wo, r1, NTOK, 1024, 1024, 1024, 1024, 1024,
        1, 0, 0, 0, 0, 0, 0, bo, x, nullptr, 1.f, xa);
    ln_kernel<<<NTOK, 256>>>(r1, y, ln1g, ln1b);

    // 6) FFN
    tgemm2<128, EPI_SILU, false><<<dim3(16, 16, 1), 256, SM128>>>(
        y, w1, u, NTOK, FFN, 1024, 1024, FFN, FFN,
        1, 0, 0, 0, 0, 0, 0, b1, nullptr, nullptr, 1.f, xa);
    tgemm2<128, EPI_RESBIAS, false><<<dim3(8, 16, 1), 256, SM128>>>(
        u, w2, r2, NTOK, 1024, FFN, FFN, 1024, 1024,
        1, 0, 0, 0, 0, 0, 0, b2, y, nullptr, 1.f, xa);
    ln_kernel<<<NTOK, 256>>>(r2, out_x, ln2g, ln2b);
}

// round 4
// speedup vs baseline: 1.3296x; 1.3296x over previous
#include <cuda_runtime.h>
#include <math_constants.h>

#define NTOK  2048
#define FFN   2048

// ---------------- scratch ----------------
__device__ float g_q   [NTOK * 1024];
__device__ float g_kt  [2 * 1024 * 1024];
__device__ float g_v   [NTOK * 1024];
__device__ float g_gate[NTOK * 1024];
__device__ float g_s   [(size_t)2 * 16 * 1024 * 1024];
__device__ float g_o   [NTOK * 1024];
__device__ float g_r1  [NTOK * 1024];
__device__ float g_y   [NTOK * 1024];
__device__ float g_u   [NTOK * FFN];
__device__ float g_r2  [NTOK * 1024];

enum { EPI_PROJ4 = 0, EPI_SCOREBIAS = 1, EPI_GATE = 2, EPI_RESBIAS = 3, EPI_SILU = 4 };

struct XArgs {
    const float* Bw1; const float* Bw2; const float* Bw3;  // wk, wv, wg
    float* Ckt; float* Cv; float* Cg;                      // kt, v, gate outputs
    const float* bg;                                       // gate bias
    const float* eb;                                       // edge bias [b,q,k,h]
};

__device__ __forceinline__ unsigned f2tf32(float f) {
    unsigned r;
    asm("cvt.rna.tf32.f32 %0, %1;" : "=r"(r) : "f"(f));
    return r;
}

__device__ __forceinline__ void cp16(unsigned dst, const void* src, bool pred) {
    int sz = pred ? 16 : 0;
    asm volatile("cp.async.cg.shared.global [%0], [%1], 16, %2;"
                 :: "r"(dst), "l"(src), "r"(sz));
}

__device__ __forceinline__ void mma_tf32(float* c, const unsigned* a, const unsigned* b) {
    asm volatile(
        "mma.sync.aligned.m16n8k8.row.col.f32.tf32.tf32.f32 "
        "{%0,%1,%2,%3}, {%4,%5,%6,%7}, {%8,%9}, {%0,%1,%2,%3};"
        : "+f"(c[0]), "+f"(c[1]), "+f"(c[2]), "+f"(c[3])
        : "r"(a[0]), "r"(a[1]), "r"(a[2]), "r"(a[3]), "r"(b[0]), "r"(b[1]));
}

// ===== cp.async double-buffered TF32 GEMM (R2 pipeline), templated BN ======
template<int BN, int EPI, bool ZX>
__global__ __launch_bounds__(256, 2)
void tgemm(const float* __restrict__ A, const float* __restrict__ B,
           float* __restrict__ C, int M, int N, int K,
           int lda, int ldb, int ldc, int zdiv,
           long long sA1, long long sA2, long long sB1, long long sB2,
           long long sC1, long long sC2,
           const float* __restrict__ bias, const float* __restrict__ res,
           const unsigned char* __restrict__ mask, XArgs xa)
{
    constexpr int BM = 128, BK = 16, AS = 20, BS = BN + 8;
    constexpr int MT = 2;
    constexpr int NT = BN / 16;           // 8 (BN=128) or 4 (BN=64)
    constexpr int WN = BN / 2;            // warp n-tile

    __shared__ float As_[2][BM * AS];
    __shared__ float Bs_[2][BK * BS];

    int z, bn, bm;
    if (ZX) { z = blockIdx.x; bn = blockIdx.y; bm = blockIdx.z; }
    else    { z = blockIdx.z; bn = blockIdx.x; bm = blockIdx.y; }
    int z1 = z / zdiv, z2 = z - z1 * zdiv;
    A += (size_t)z1 * sA1 + (size_t)z2 * sA2;
    size_t coff = (size_t)z1 * sC1 + (size_t)z2 * sC2;

    const float* Bbase = B;
    int bnoff = bn * BN;
    int bsel = 0;
    if (EPI == EPI_PROJ4) {
        bsel = bn >> 3;                  // 8 col-tiles of 128 per weight
        bnoff = (bn & 7) * 128;
        Bbase = (bsel == 0) ? B : (bsel == 1) ? xa.Bw1 : (bsel == 2) ? xa.Bw2 : xa.Bw3;
    } else {
        Bbase += (size_t)z1 * sB1 + (size_t)z2 * sB2;
    }

    int tid = threadIdx.x, lane = tid & 31, wid = tid >> 5;
    int wm = (wid & 3) * 32;
    int wn = (wid >> 2) * WN;

    unsigned as_base = (unsigned)__cvta_generic_to_shared(As_);
    unsigned bs_base = (unsigned)__cvta_generic_to_shared(Bs_);

    const float* Ag = A + (size_t)(bm * BM) * lda;
    const float* Bg = Bbase + bnoff;

    float acc[MT][NT][4] = {};

    constexpr int ALD = 2;                       // 128*16/(256*4)
    constexpr int BLD = (BK * BN) / (256 * 4);   // 2 or 1

    int KT = K / BK;

    // prologue: stage 0
    {
#pragma unroll
        for (int i = 0; i < ALD; i++) {
            int f = tid + 256 * i;
            int row = f >> 2, c4 = (f & 3) * 4;
            cp16(as_base + (unsigned)(row * AS + c4) * 4,
                 Ag + (size_t)row * lda + c4, true);
        }
#pragma unroll
        for (int i = 0; i < BLD; i++) {
            int f = tid + 256 * i;
            int row = f / (BN / 4), c4 = (f % (BN / 4)) * 4;
            cp16(bs_base + (unsigned)(row * BS + c4) * 4,
                 Bg + (size_t)row * ldb + c4, (bnoff + c4) < N);
        }
        asm volatile("cp.async.commit_group;");
    }

    for (int kt = 0; kt < KT; kt++) {
        int st = kt & 1;
        if (kt + 1 < KT) {
            int ns = st ^ 1;
            int k0 = (kt + 1) * BK;
#pragma unroll
            for (int i = 0; i < ALD; i++) {
                int f = tid + 256 * i;
                int row = f >> 2, c4 = (f & 3) * 4;
                cp16(as_base + (unsigned)(ns * BM * AS + row * AS + c4) * 4,
                     Ag + (size_t)row * lda + k0 + c4, true);
            }
#pragma unroll
            for (int i = 0; i < BLD; i++) {
                int f = tid + 256 * i;
                int row = f / (BN / 4), c4 = (f % (BN / 4)) * 4;
                cp16(bs_base + (unsigned)(ns * BK * BS + row * BS + c4) * 4,
                     Bg + (size_t)(k0 + row) * ldb + c4, (bnoff + c4) < N);
            }
            asm volatile("cp.async.commit_group;");
            asm volatile("cp.async.wait_group %0;" :: "n"(1));
        } else {
            asm volatile("cp.async.wait_group %0;" :: "n"(0));
        }
        __syncthreads();

        const float* Asr = As_[st];
        const float* Bsr = Bs_[st];
#pragma unroll
        for (int kk = 0; kk < 16; kk += 8) {
            unsigned a[MT][4], b[NT][2];
            int ar = lane >> 2, ac = kk + (lane & 3);
#pragma unroll
            for (int m_ = 0; m_ < MT; m_++) {
                int r = wm + m_ * 16 + ar;
                a[m_][0] = f2tf32(Asr[r * AS + ac]);
                a[m_][1] = f2tf32(Asr[(r + 8) * AS + ac]);
                a[m_][2] = f2tf32(Asr[r * AS + ac + 4]);
                a[m_][3] = f2tf32(Asr[(r + 8) * AS + ac + 4]);
            }
            int br = kk + (lane & 3), bc = wn + (lane >> 2);
#pragma unroll
            for (int n_ = 0; n_ < NT; n_++) {
                b[n_][0] = f2tf32(Bsr[br * BS + bc + n_ * 8]);
                b[n_][1] = f2tf32(Bsr[(br + 4) * BS + bc + n_ * 8]);
            }
#pragma unroll
            for (int m_ = 0; m_ < MT; m_++)
#pragma unroll
                for (int n_ = 0; n_ < NT; n_++)
                    mma_tf32(acc[m_][n_], a[m_], b[n_]);
        }
        __syncthreads();
    }

    // epilogue
#pragma unroll
    for (int m_ = 0; m_ < MT; m_++) {
#pragma unroll
        for (int n_ = 0; n_ < NT; n_++) {
#pragma unroll
            for (int e = 0; e < 4; e++) {
                int m = bm * BM + wm + m_ * 16 + (lane >> 2) + (e >> 1) * 8;
                int n = bnoff + wn + n_ * 8 + (lane & 3) * 2 + (e & 1);
                if (n >= N) continue;
                float v = acc[m_][n_][e];
                size_t idx = coff + (size_t)m * ldc + n;
                if (EPI == EPI_PROJ4) {
                    if (bsel == 0) {
                        C[idx] = v * 0.125f;
                    } else if (bsel == 1) {
                        size_t o = (size_t)(m >> 10) * (1u << 20) + (size_t)n * 1024 + (m & 1023);
                        xa.Ckt[o] = v;
                    } else if (bsel == 2) {
                        xa.Cv[idx] = v;
                    } else {
                        float zz = v + xa.bg[n];
                        xa.Cg[idx] = 1.f / (1.f + __expf(-zz));
                    }
                } else if (EPI == EPI_SCOREBIAS) {
                    float t = v + xa.eb[((size_t)(z1 * 1024 + m) * 1024 + n) * 16 + z2];
                    if (mask[z1 * 1024 + n]) t = -CUDART_INF_F;
                    C[idx] = t;
                } else if (EPI == EPI_GATE) {
                    C[idx] = v * res[idx];
                } else if (EPI == EPI_RESBIAS) {
                    C[idx] = v + bias[n] + res[idx];
                } else if (EPI == EPI_SILU) {
                    float zz = v + bias[n];
                    C[idx] = zz / (1.f + __expf(-zz));
                }
            }
        }
    }
}

// ------- softmax over k; probs back to g_s and d_out [b,q,k,h] -------------
__global__ __launch_bounds__(512)
void softmax_kernel(float* __restrict__ s, float* __restrict__ attn_out)
{
    int q = blockIdx.x;
    int b = blockIdx.y;
    int w    = threadIdx.x >> 5;
    int lane = threadIdx.x & 31;
    float* row = s + (((size_t)(b * 16 + w) * 1024 + q)) * 1024;

    float v[32];
    float mx = -CUDART_INF_F;
#pragma unroll
    for (int i = 0; i < 32; i++) {
        v[i] = row[i * 32 + lane];
        mx = fmaxf(mx, v[i]);
    }
#pragma unroll
    for (int o = 16; o; o >>= 1) mx = fmaxf(mx, __shfl_xor_sync(0xffffffffu, mx, o));
    float sum = 0.f;
#pragma unroll
    for (int i = 0; i < 32; i++) { v[i] = __expf(v[i] - mx); sum += v[i]; }
#pragma unroll
    for (int o = 16; o; o >>= 1) sum += __shfl_xor_sync(0xffffffffu, sum, o);
    float inv = 1.f / sum;
#pragma unroll
    for (int i = 0; i < 32; i++) { v[i] *= inv; row[i * 32 + lane] = v[i]; }

    __shared__ float tile[16 * 513];
    float* out = attn_out + ((size_t)(b * 1024 + q)) * 16384;
#pragma unroll
    for (int half = 0; half < 2; half++) {
        __syncthreads();
#pragma unroll
        for (int i = 0; i < 16; i++) {
            int k = (half * 16 + i) * 32 + lane;
            tile[w * 513 + (k - half * 512)] = v[half * 16 + i];
        }
        __syncthreads();
        for (int idx = threadIdx.x; idx < 8192; idx += 512) {
            int k = idx >> 4, h = idx & 15;
            out[half * 8192 + idx] = tile[h * 513 + k];
        }
    }
}

// ---------------- row LayerNorm over D=1024 --------------------------------
__global__ __launch_bounds__(256)
void ln_kernel(const float* __restrict__ in, float* __restrict__ out,
               const float* __restrict__ gg, const float* __restrict__ bb)
{
    int row = blockIdx.x;
    int tid = threadIdx.x;
    float4 v = reinterpret_cast<const float4*>(in + (size_t)row * 1024)[tid];
    float s  = v.x + v.y + v.z + v.w;
    float ss = v.x * v.x + v.y * v.y + v.z * v.z + v.w * v.w;
#pragma unroll
    for (int o = 16; o; o >>= 1) {
        s  += __shfl_xor_sync(0xffffffffu, s, o);
        ss += __shfl_xor_sync(0xffffffffu, ss, o);
    }
    __shared__ float rs[8], rss[8];
    if ((tid & 31) == 0) { rs[tid >> 5] = s; rss[tid >> 5] = ss; }
    __syncthreads();
    if (tid < 32) {
        float a = (tid < 8) ? rs[tid] : 0.f;
        float c = (tid < 8) ? rss[tid] : 0.f;
#pragma unroll
        for (int o = 4; o; o >>= 1) {
            a += __shfl_xor_sync(0xffffffffu, a, o);
            c += __shfl_xor_sync(0xffffffffu, c, o);
        }
        if (tid == 0) { rs[0] = a; rss[0] = c; }
    }
    __syncthreads();
    float mean = rs[0] * (1.f / 1024.f);
    float var  = rss[0] * (1.f / 1024.f) - mean * mean;
    float inv  = rsqrtf(var + 1e-5f);
    float4 g4 = ((const float4*)gg)[tid];
    float4 b4 = ((const float4*)bb)[tid];
    float4 o4;
    o4.x = (v.x - mean) * inv * g4.x + b4.x;
    o4.y = (v.y - mean) * inv * g4.y + b4.y;
    o4.z = (v.z - mean) * inv * g4.z + b4.z;
    o4.w = (v.w - mean) * inv * g4.w + b4.w;
    reinterpret_cast<float4*>(out + (size_t)row * 1024)[tid] = o4;
}

// ---------------- launcher --------------------------------------------------
extern "C" void kernel_launch(void* const* d_in, const int* in_sizes, int n_in,
                              void* d_out, int out_size)
{
    const float* x    = (const float*)d_in[0];
    const float* eb   = (const float*)d_in[1];
    const unsigned char* mask = (const unsigned char*)d_in[2];
    const float* wq   = (const float*)d_in[3];
    const float* wk   = (const float*)d_in[4];
    const float* wv   = (const float*)d_in[5];
    const float* wo   = (const float*)d_in[6];
    const float* bo   = (const float*)d_in[7];
    const float* wg   = (const float*)d_in[8];
    const float* bg   = (const float*)d_in[9];
    const float* w1   = (const float*)d_in[10];
    const float* b1   = (const float*)d_in[11];
    const float* w2   = (const float*)d_in[12];
    const float* b2   = (const float*)d_in[13];
    const float* ln1g = (const float*)d_in[14];
    const float* ln1b = (const float*)d_in[15];
    const float* ln2g = (const float*)d_in[16];
    const float* ln2b = (const float*)d_in[17];

    float* out_x    = (float*)d_out;
    float* out_attn = (float*)d_out + (size_t)NTOK * 1024;

    float *q, *kt, *v, *g, *s, *o, *r1, *y, *u, *r2;
    cudaGetSymbolAddress((void**)&q,  g_q);
    cudaGetSymbolAddress((void**)&kt, g_kt);
    cudaGetSymbolAddress((void**)&v,  g_v);
    cudaGetSymbolAddress((void**)&g,  g_gate);
    cudaGetSymbolAddress((void**)&s,  g_s);
    cudaGetSymbolAddress((void**)&o,  g_o);
    cudaGetSymbolAddress((void**)&r1, g_r1);
    cudaGetSymbolAddress((void**)&y,  g_y);
    cudaGetSymbolAddress((void**)&u,  g_u);
    cudaGetSymbolAddress((void**)&r2, g_r2);

    XArgs xa{};
    xa.bg = bg; xa.eb = eb;

    // 1) fused projections: q(scaled), kt(transposed), v, gate  [one launch]
    {
        XArgs pa = xa;
        pa.Bw1 = wk; pa.Bw2 = wv; pa.Bw3 = wg;
        pa.Ckt = kt; pa.Cv = v;  pa.Cg = g;
        tgemm<128, EPI_PROJ4, false><<<dim3(32, 16, 1), 256>>>(
            x, wq, q, NTOK, 1024, 1024, 1024, 1024, 1024,
            1, 0, 0, 0, 0, 0, 0, nullptr, nullptr, nullptr, pa);
    }

    // 2) scores = Q_h @ Kt_h + edge_bias (direct read; z fastest for L2 share)
    tgemm<128, EPI_SCOREBIAS, true><<<dim3(32, 8, 8), 256>>>(
        q, kt, s, 1024, 1024, 64, 1024, 1024, 1024,
        16,
        (long long)1048576, 64,
        (long long)1048576, 65536,
        (long long)16777216, 1048576,
        nullptr, nullptr, mask, xa);

    // 3) softmax over keys; probs to g_s and d_out [b,q,k,h]
    softmax_kernel<<<dim3(1024, 2), 512>>>(s, out_attn);

    // 4) o = (probs @ V_h) * gate   (BN=64 tile, no wasted columns)
    tgemm<64, EPI_GATE, true><<<dim3(32, 1, 8), 256>>>(
        s, v, o, 1024, 64, 1024, 1024, 1024, 1024,
        16,
        (long long)16777216, 1048576,
        (long long)1048576, 64,
        (long long)1048576, 64,
        nullptr, g, nullptr, xa);

    // 5) r1 = o @ wo + bo + x ; LN1 -> y
    tgemm<128, EPI_RESBIAS, false><<<dim3(8, 16, 1), 256>>>(
        o, wo, r1, NTOK, 1024, 1024, 1024, 1024, 1024,
        1, 0, 0, 0, 0, 0, 0, bo, x, nullptr, xa);
    ln_kernel<<<NTOK, 256>>>(r1, y, ln1g, ln1b);

    // 6) FFN
    tgemm<128, EPI_SILU, false><<<dim3(16, 16, 1), 256>>>(
        y, w1, u, NTOK, FFN, 1024, 1024, FFN, FFN,
        1, 0, 0, 0, 0, 0, 0, b1, nullptr, nullptr, xa);
    tgemm<128, EPI_RESBIAS, false><<<dim3(8, 16, 1), 256>>>(
        u, w2, r2, NTOK, 1024, FFN, FFN, 1024, 1024,
        1, 0, 0, 0, 0, 0, 0, b2, y, nullptr, xa);
    ln_kernel<<<NTOK, 256>>>(r2, out_x, ln2g, ln2b);
}

// round 5
// speedup vs baseline: 1.4753x; 1.1096x over previous
#include <cuda_runtime.h>
#include <math_constants.h>

#define NTOK  2048
#define FFN   2048

// ---------------- scratch ----------------
__device__ float g_q   [NTOK * 1024];
__device__ float g_kt  [2 * 1024 * 1024];
__device__ float g_v   [NTOK * 1024];
__device__ float g_gate[NTOK * 1024];
__device__ float g_s   [(size_t)2 * 16 * 1024 * 1024];
__device__ float g_o   [NTOK * 1024];
__device__ float g_r1  [NTOK * 1024];
__device__ float g_y   [NTOK * 1024];
__device__ float g_u   [NTOK * FFN];
__device__ float g_r2  [NTOK * 1024];

enum { EPI_PROJ4 = 0, EPI_SCOREBIAS = 1, EPI_GATE = 2, EPI_RESBIAS = 3, EPI_SILU = 4 };

struct XArgs {
    const float* Bw1; const float* Bw2; const float* Bw3;  // wk, wv, wg
    float* Ckt; float* Cv; float* Cg;                      // kt, v, gate outputs
    const float* bg;                                       // gate bias
    const float* eb;                                       // edge bias [b,q,k,h]
};

__device__ __forceinline__ void cp16(unsigned dst, const void* src, bool pred) {
    int sz = pred ? 16 : 0;
    asm volatile("cp.async.cg.shared.global [%0], [%1], 16, %2;"
                 :: "r"(dst), "l"(src), "r"(sz));
}

__device__ __forceinline__ void mma_tf32(float* c, const unsigned* a, const unsigned* b) {
    asm volatile(
        "mma.sync.aligned.m16n8k8.row.col.f32.tf32.tf32.f32 "
        "{%0,%1,%2,%3}, {%4,%5,%6,%7}, {%8,%9}, {%0,%1,%2,%3};"
        : "+f"(c[0]), "+f"(c[1]), "+f"(c[2]), "+f"(c[3])
        : "r"(a[0]), "r"(a[1]), "r"(a[2]), "r"(a[3]), "r"(b[0]), "r"(b[1]));
}

// ====== cp.async double-buffered TF32 GEMM, BK=32, no explicit cvt =========
template<int BN, int EPI, bool ZX>
__global__ __launch_bounds__(256, 2)
void tgemm(const float* __restrict__ A, const float* __restrict__ B,
           float* __restrict__ C, int M, int N, int K,
           int lda, int ldb, int ldc, int zdiv,
           long long sA1, long long sA2, long long sB1, long long sB2,
           long long sC1, long long sC2,
           const float* __restrict__ bias, const float* __restrict__ res,
           const unsigned char* __restrict__ mask, XArgs xa)
{
    constexpr int BM = 128, BK = 32, AS = BK + 4, BS = BN + 8;
    constexpr int MT = 2;
    constexpr int NT = BN / 16;           // 8 (BN=128) or 4 (BN=64)
    constexpr int WN = BN / 2;            // warp n-tile

    extern __shared__ float smem[];
    float* As_ = smem;                       // [2][BM*AS]
    float* Bs_ = smem + 2 * BM * AS;         // [2][BK*BS]

    int z, bn, bm;
    if (ZX) { z = blockIdx.x; bn = blockIdx.y; bm = blockIdx.z; }
    else    { z = blockIdx.z; bn = blockIdx.x; bm = blockIdx.y; }
    int z1 = z / zdiv, z2 = z - z1 * zdiv;
    A += (size_t)z1 * sA1 + (size_t)z2 * sA2;
    size_t coff = (size_t)z1 * sC1 + (size_t)z2 * sC2;

    const float* Bbase = B;
    int bnoff = bn * BN;
    int bsel = 0;
    if (EPI == EPI_PROJ4) {
        bsel = bn >> 3;                  // 8 col-tiles of 128 per weight
        bnoff = (bn & 7) * 128;
        Bbase = (bsel == 0) ? B : (bsel == 1) ? xa.Bw1 : (bsel == 2) ? xa.Bw2 : xa.Bw3;
    } else {
        Bbase += (size_t)z1 * sB1 + (size_t)z2 * sB2;
    }

    int tid = threadIdx.x, lane = tid & 31, wid = tid >> 5;
    int wm = (wid & 3) * 32;
    int wn = (wid >> 2) * WN;

    unsigned as_base = (unsigned)__cvta_generic_to_shared(As_);
    unsigned bs_base = (unsigned)__cvta_generic_to_shared(Bs_);

    const float* Ag = A + (size_t)(bm * BM) * lda;
    const float* Bg = Bbase + bnoff;

    float acc[MT][NT][4] = {};

    constexpr int ALD = (BM * BK) / (256 * 4);   // 4
    constexpr int BLD = (BK * BN) / (256 * 4);   // 4 or 2

    int KT = K / BK;

    // prologue: stage 0
    {
#pragma unroll
        for (int i = 0; i < ALD; i++) {
            int f = tid + 256 * i;
            int row = f >> 3, c4 = (f & 7) * 4;
            cp16(as_base + (unsigned)(row * AS + c4) * 4,
                 Ag + (size_t)row * lda + c4, true);
        }
#pragma unroll
        for (int i = 0; i < BLD; i++) {
            int f = tid + 256 * i;
            int row = f / (BN / 4), c4 = (f % (BN / 4)) * 4;
            cp16(bs_base + (unsigned)(row * BS + c4) * 4,
                 Bg + (size_t)row * ldb + c4, (bnoff + c4) < N);
        }
        asm volatile("cp.async.commit_group;");
    }

    for (int kt = 0; kt < KT; kt++) {
        int st = kt & 1;
        if (kt + 1 < KT) {
            int ns = st ^ 1;
            int k0 = (kt + 1) * BK;
#pragma unroll
            for (int i = 0; i < ALD; i++) {
                int f = tid + 256 * i;
                int row = f >> 3, c4 = (f & 7) * 4;
                cp16(as_base + (unsigned)(ns * BM * AS + row * AS + c4) * 4,
                     Ag + (size_t)row * lda + k0 + c4, true);
            }
#pragma unroll
            for (int i = 0; i < BLD; i++) {
                int f = tid + 256 * i;
                int row = f / (BN / 4), c4 = (f % (BN / 4)) * 4;
                cp16(bs_base + (unsigned)(ns * BK * BS + row * BS + c4) * 4,
                     Bg + (size_t)(k0 + row) * ldb + c4, (bnoff + c4) < N);
            }
            asm volatile("cp.async.commit_group;");
            asm volatile("cp.async.wait_group %0;" :: "n"(1));
        } else {
            asm volatile("cp.async.wait_group %0;" :: "n"(0));
        }
        __syncthreads();

        const float* Asr = As_ + st * BM * AS;
        const float* Bsr = Bs_ + st * BK * BS;
#pragma unroll
        for (int kk = 0; kk < BK; kk += 8) {
            unsigned a[MT][4], b[NT][2];
            int ar = lane >> 2, ac = kk + (lane & 3);
#pragma unroll
            for (int m_ = 0; m_ < MT; m_++) {
                int r = wm + m_ * 16 + ar;
                a[m_][0] = __float_as_uint(Asr[r * AS + ac]);
                a[m_][1] = __float_as_uint(Asr[(r + 8) * AS + ac]);
                a[m_][2] = __float_as_uint(Asr[r * AS + ac + 4]);
                a[m_][3] = __float_as_uint(Asr[(r + 8) * AS + ac + 4]);
            }
            int br = kk + (lane & 3), bc = wn + (lane >> 2);
#pragma unroll
            for (int n_ = 0; n_ < NT; n_++) {
                b[n_][0] = __float_as_uint(Bsr[br * BS + bc + n_ * 8]);
                b[n_][1] = __float_as_uint(Bsr[(br + 4) * BS + bc + n_ * 8]);
            }
#pragma unroll
            for (int m_ = 0; m_ < MT; m_++)
#pragma unroll
                for (int n_ = 0; n_ < NT; n_++)
                    mma_tf32(acc[m_][n_], a[m_], b[n_]);
        }
        __syncthreads();
    }

    // epilogue
#pragma unroll
    for (int m_ = 0; m_ < MT; m_++) {
#pragma unroll
        for (int n_ = 0; n_ < NT; n_++) {
#pragma unroll
            for (int e = 0; e < 4; e++) {
                int m = bm * BM + wm + m_ * 16 + (lane >> 2) + (e >> 1) * 8;
                int n = bnoff + wn + n_ * 8 + (lane & 3) * 2 + (e & 1);
                if (n >= N) continue;
                float v = acc[m_][n_][e];
                size_t idx = coff + (size_t)m * ldc + n;
                if (EPI == EPI_PROJ4) {
                    if (bsel == 0) {
                        C[idx] = v * 0.125f;
                    } else if (bsel == 1) {
                        size_t o = (size_t)(m >> 10) * (1u << 20) + (size_t)n * 1024 + (m & 1023);
                        xa.Ckt[o] = v;
                    } else if (bsel == 2) {
                        xa.Cv[idx] = v;
                    } else {
                        float zz = v + xa.bg[n];
                        xa.Cg[idx] = 1.f / (1.f + __expf(-zz));
                    }
                } else if (EPI == EPI_SCOREBIAS) {
                    float t = v + xa.eb[((size_t)(z1 * 1024 + m) * 1024 + n) * 16 + z2];
                    if (mask[z1 * 1024 + n]) t = -CUDART_INF_F;
                    C[idx] = t;
                } else if (EPI == EPI_GATE) {
                    C[idx] = v * res[idx];
                } else if (EPI == EPI_RESBIAS) {
                    C[idx] = v + bias[n] + res[idx];
                } else if (EPI == EPI_SILU) {
                    float zz = v + bias[n];
                    C[idx] = zz / (1.f + __expf(-zz));
                }
            }
        }
    }
}

// ------- softmax over k; probs back to g_s and d_out [b,q,k,h] -------------
__global__ __launch_bounds__(512)
void softmax_kernel(float* __restrict__ s, float* __restrict__ attn_out)
{
    int q = blockIdx.x;
    int b = blockIdx.y;
    int w    = threadIdx.x >> 5;
    int lane = threadIdx.x & 31;
    float* row = s + (((size_t)(b * 16 + w) * 1024 + q)) * 1024;

    float v[32];
    float mx = -CUDART_INF_F;
#pragma unroll
    for (int i = 0; i < 32; i++) {
        v[i] = row[i * 32 + lane];
        mx = fmaxf(mx, v[i]);
    }
#pragma unroll
    for (int o = 16; o; o >>= 1) mx = fmaxf(mx, __shfl_xor_sync(0xffffffffu, mx, o));
    float sum = 0.f;
#pragma unroll
    for (int i = 0; i < 32; i++) { v[i] = __expf(v[i] - mx); sum += v[i]; }
#pragma unroll
    for (int o = 16; o; o >>= 1) sum += __shfl_xor_sync(0xffffffffu, sum, o);
    float inv = 1.f / sum;
#pragma unroll
    for (int i = 0; i < 32; i++) { v[i] *= inv; row[i * 32 + lane] = v[i]; }

    __shared__ float tile[16 * 513];
    float* out = attn_out + ((size_t)(b * 1024 + q)) * 16384;
#pragma unroll
    for (int half = 0; half < 2; half++) {
        __syncthreads();
#pragma unroll
        for (int i = 0; i < 16; i++) {
            int k = (half * 16 + i) * 32 + lane;
            tile[w * 513 + (k - half * 512)] = v[half * 16 + i];
        }
        __syncthreads();
        for (int idx = threadIdx.x; idx < 8192; idx += 512) {
            int k = idx >> 4, h = idx & 15;
            out[half * 8192 + idx] = tile[h * 513 + k];
        }
    }
}

// ---------------- row LayerNorm over D=1024 --------------------------------
__global__ __launch_bounds__(256)
void ln_kernel(const float* __restrict__ in, float* __restrict__ out,
               const float* __restrict__ gg, const float* __restrict__ bb)
{
    int row = blockIdx.x;
    int tid = threadIdx.x;
    float4 v = reinterpret_cast<const float4*>(in + (size_t)row * 1024)[tid];
    float s  = v.x + v.y + v.z + v.w;
    float ss = v.x * v.x + v.y * v.y + v.z * v.z + v.w * v.w;
#pragma unroll
    for (int o = 16; o; o >>= 1) {
        s  += __shfl_xor_sync(0xffffffffu, s, o);
        ss += __shfl_xor_sync(0xffffffffu, ss, o);
    }
    __shared__ float rs[8], rss[8];
    if ((tid & 31) == 0) { rs[tid >> 5] = s; rss[tid >> 5] = ss; }
    __syncthreads();
    if (tid < 32) {
        float a = (tid < 8) ? rs[tid] : 0.f;
        float c = (tid < 8) ? rss[tid] : 0.f;
#pragma unroll
        for (int o = 4; o; o >>= 1) {
            a += __shfl_xor_sync(0xffffffffu, a, o);
            c += __shfl_xor_sync(0xffffffffu, c, o);
        }
        if (tid == 0) { rs[0] = a; rss[0] = c; }
    }
    __syncthreads();
    float mean = rs[0] * (1.f / 1024.f);
    float var  = rss[0] * (1.f / 1024.f) - mean * mean;
    float inv  = rsqrtf(var + 1e-5f);
    float4 g4 = ((const float4*)gg)[tid];
    float4 b4 = ((const float4*)bb)[tid];
    float4 o4;
    o4.x = (v.x - mean) * inv * g4.x + b4.x;
    o4.y = (v.y - mean) * inv * g4.y + b4.y;
    o4.z = (v.z - mean) * inv * g4.z + b4.z;
    o4.w = (v.w - mean) * inv * g4.w + b4.w;
    reinterpret_cast<float4*>(out + (size_t)row * 1024)[tid] = o4;
}

// ---------------- launcher --------------------------------------------------
extern "C" void kernel_launch(void* const* d_in, const int* in_sizes, int n_in,
                              void* d_out, int out_size)
{
    const float* x    = (const float*)d_in[0];
    const float* eb   = (const float*)d_in[1];
    const unsigned char* mask = (const unsigned char*)d_in[2];
    const float* wq   = (const float*)d_in[3];
    const float* wk   = (const float*)d_in[4];
    const float* wv   = (const float*)d_in[5];
    const float* wo   = (const float*)d_in[6];
    const float* bo   = (const float*)d_in[7];
    const float* wg   = (const float*)d_in[8];
    const float* bg   = (const float*)d_in[9];
    const float* w1   = (const float*)d_in[10];
    const float* b1   = (const float*)d_in[11];
    const float* w2   = (const float*)d_in[12];
    const float* b2   = (const float*)d_in[13];
    const float* ln1g = (const float*)d_in[14];
    const float* ln1b = (const float*)d_in[15];
    const float* ln2g = (const float*)d_in[16];
    const float* ln2b = (const float*)d_in[17];

    float* out_x    = (float*)d_out;
    float* out_attn = (float*)d_out + (size_t)NTOK * 1024;

    float *q, *kt, *v, *g, *s, *o, *r1, *y, *u, *r2;
    cudaGetSymbolAddress((void**)&q,  g_q);
    cudaGetSymbolAddress((void**)&kt, g_kt);
    cudaGetSymbolAddress((void**)&v,  g_v);
    cudaGetSymbolAddress((void**)&g,  g_gate);
    cudaGetSymbolAddress((void**)&s,  g_s);
    cudaGetSymbolAddress((void**)&o,  g_o);
    cudaGetSymbolAddress((void**)&r1, g_r1);
    cudaGetSymbolAddress((void**)&y,  g_y);
    cudaGetSymbolAddress((void**)&u,  g_u);
    cudaGetSymbolAddress((void**)&r2, g_r2);

    // dynamic smem sizes: 2*(128*36) + 2*(32*(BN+8)) floats
    const int SM128 = (2 * 128 * 36 + 2 * 32 * 136) * 4;  // 71680
    const int SM64  = (2 * 128 * 36 + 2 * 32 * 72) * 4;   // 55296
    cudaFuncSetAttribute(tgemm<128, EPI_PROJ4, false>,
                         cudaFuncAttributeMaxDynamicSharedMemorySize, SM128);
    cudaFuncSetAttribute(tgemm<128, EPI_SCOREBIAS, true>,
                         cudaFuncAttributeMaxDynamicSharedMemorySize, SM128);
    cudaFuncSetAttribute(tgemm<64, EPI_GATE, true>,
                         cudaFuncAttributeMaxDynamicSharedMemorySize, SM64);
    cudaFuncSetAttribute(tgemm<128, EPI_RESBIAS, false>,
                         cudaFuncAttributeMaxDynamicSharedMemorySize, SM128);
    cudaFuncSetAttribute(tgemm<128, EPI_SILU, false>,
                         cudaFuncAttributeMaxDynamicSharedMemorySize, SM128);

    XArgs xa{};
    xa.bg = bg; xa.eb = eb;

    // 1) fused projections: q(scaled), kt(transposed), v, gate  [one launch]
    {
        XArgs pa = xa;
        pa.Bw1 = wk; pa.Bw2 = wv; pa.Bw3 = wg;
        pa.Ckt = kt; pa.Cv = v;  pa.Cg = g;
        tgemm<128, EPI_PROJ4, false><<<dim3(32, 16, 1), 256, SM128>>>(
            x, wq, q, NTOK, 1024, 1024, 1024, 1024, 1024,
            1, 0, 0, 0, 0, 0, 0, nullptr, nullptr, nullptr, pa);
    }

    // 2) scores = Q_h @ Kt_h + edge_bias (direct read; z fastest for L2 share)
    tgemm<128, EPI_SCOREBIAS, true><<<dim3(32, 8, 8), 256, SM128>>>(
        q, kt, s, 1024, 1024, 64, 1024, 1024, 1024,
        16,
        (long long)1048576, 64,
        (long long)1048576, 65536,
        (long long)16777216, 1048576,
        nullptr, nullptr, mask, xa);

    // 3) softmax over keys; probs to g_s and d_out [b,q,k,h]
    softmax_kernel<<<dim3(1024, 2), 512>>>(s, out_attn);

    // 4) o = (probs @ V_h) * gate   (BN=64 tile)
    tgemm<64, EPI_GATE, true><<<dim3(32, 1, 8), 256, SM64>>>(
        s, v, o, 1024, 64, 1024, 1024, 1024, 1024,
        16,
        (long long)16777216, 1048576,
        (long long)1048576, 64,
        (long long)1048576, 64,
        nullptr, g, nullptr, xa);

    // 5) r1 = o @ wo + bo + x ; LN1 -> y
    tgemm<128, EPI_RESBIAS, false><<<dim3(8, 16, 1), 256, SM128>>>(
        o, wo, r1, NTOK, 1024, 1024, 1024, 1024, 1024,
        1, 0, 0, 0, 0, 0, 0, bo, x, nullptr, xa);
    ln_kernel<<<NTOK, 256>>>(r1, y, ln1g, ln1b);

    // 6) FFN
    tgemm<128, EPI_SILU, false><<<dim3(16, 16, 1), 256, SM128>>>(
        y, w1, u, NTOK, FFN, 1024, 1024, FFN, FFN,
        1, 0, 0, 0, 0, 0, 0, b1, nullptr, nullptr, xa);
    tgemm<128, EPI_RESBIAS, false><<<dim3(8, 16, 1), 256, SM128>>>(
        u, w2, r2, NTOK, 1024, FFN, FFN, 1024, 1024,
        1, 0, 0, 0, 0, 0, 0, b2, y, nullptr, xa);
    ln_kernel<<<NTOK, 256>>>(r2, out_x, ln2g, ln2b);
}